// round 7
// baseline (speedup 1.0000x reference)
#include <cuda_runtime.h>
#include <cuda_bf16.h>
#include <cstdint>

#define M_DIM 16384
#define N_DIM 8192
#define K_DIM 64

#define THREADS 128            // 4 warps
#define M_CTA 128              // warp covers 32 m
#define NSPLIT 4
#define NRANGE (N_DIM / NSPLIT)      // 2048
#define NSTEPS (NRANGE / 16)         // 128 per CTA

#define BFRAG_U32 (512 * 4 * 2 * 128)   // real fragments
#define NPAIRS (N_DIM / 2)

typedef unsigned long long ull;

// ---- device scratch ----
// B fragments, mma-ready: u32 index = ((s*4 + ktp)*2 + h)*128 + lane*4 + j
// padded by one step (8*128 u32) so cross-step prefetch never reads OOB
__device__ uint32_t g_Bfrag[BFRAG_U32 + 8 * 128];
__device__ float g_Xpk[NPAIRS * 8];                      // per n-pair, eps-scaled, negated
__device__ float g_part[NSPLIT][M_DIM * K_DIM];          // partials, 16MB

// ---- helpers ----
__device__ __forceinline__ ull ffma2(ull a, ull b, ull c) {
    ull d; asm("fma.rn.f32x2 %0, %1, %2, %3;" : "=l"(d) : "l"(a), "l"(b), "l"(c)); return d;
}
__device__ __forceinline__ ull fadd2(ull a, ull b) {
    ull d; asm("add.rn.f32x2 %0, %1, %2;" : "=l"(d) : "l"(a), "l"(b)); return d;
}
__device__ __forceinline__ ull splat2(float v) {
    ull d; asm("mov.b64 %0, {%1, %1};" : "=l"(d) : "f"(v)); return d;
}
__device__ __forceinline__ void unpack2(ull p, float& lo, float& hi) {
    asm("mov.b64 {%0, %1}, %2;" : "=f"(lo), "=f"(hi) : "l"(p));
}
__device__ __forceinline__ float fast_sqrt(float x) {
    float r; asm("sqrt.approx.f32 %0, %1;" : "=f"(r) : "f"(x)); return r;
}
__device__ __forceinline__ void mma_bf16(float* d, uint32_t a0, uint32_t a1,
                                         uint32_t a2, uint32_t a3,
                                         uint32_t b0, uint32_t b1) {
    asm volatile(
        "mma.sync.aligned.m16n8k16.row.col.f32.bf16.bf16.f32 "
        "{%0,%1,%2,%3}, {%4,%5,%6,%7}, {%8,%9}, {%0,%1,%2,%3};"
        : "+f"(d[0]), "+f"(d[1]), "+f"(d[2]), "+f"(d[3])
        : "r"(a0), "r"(a1), "r"(a2), "r"(a3), "r"(b0), "r"(b1));
}

// ---- merged prep: X pairs + W fragment shredding (hi/lo bf16 split) ----
__global__ __launch_bounds__(256)
void prep_all(const float* __restrict__ W, const float* __restrict__ X,
              const float* __restrict__ epsp) {
    int idx = blockIdx.x * 256 + threadIdx.x;

    if (idx < NPAIRS) {
        float e = *epsp;
        const float* x0 = X + (size_t)(2 * idx) * 3;
        float* o = g_Xpk + (size_t)idx * 8;
        o[0] = -e * x0[0]; o[1] = -e * x0[3];
        o[2] = -e * x0[1]; o[3] = -e * x0[4];
        o[4] = -e * x0[2]; o[5] = -e * x0[5];
        o[6] = 0.0f; o[7] = 0.0f;
    }

    // B fragment shred (idx covers all of BFRAG_U32)
    {
        int j   = idx & 3;
        int t   = (idx >> 2) & 31;
        int h   = (idx >> 7) & 1;
        int ktp = (idx >> 8) & 3;
        int s   = idx >> 10;

        int kt = ktp * 2 + (j >> 1);
        int km = (t & 3) * 2 + (j & 1) * 8;   // contraction row within step
        int nm = t >> 2;                      // output col within tile
        int kout = kt * 8 + nm;
        int n = s * 16 + km;

        float w0 = W[(size_t)kout * N_DIM + n];
        float w1 = W[(size_t)kout * N_DIM + n + 1];
        float v0, v1;
        if (h == 0) {
            v0 = __bfloat162float(__float2bfloat16(w0));
            v1 = __bfloat162float(__float2bfloat16(w1));
        } else {
            v0 = w0 - __bfloat162float(__float2bfloat16(w0));
            v1 = w1 - __bfloat162float(__float2bfloat16(w1));
        }
        uint32_t packed;
        asm("cvt.rn.bf16x2.f32 %0, %1, %2;" : "=r"(packed) : "f"(v1), "f"(v0));
        g_Bfrag[idx] = packed;
    }
}

// ---- main kernel ----
__global__ __launch_bounds__(THREADS, 4)
void rbf_hmma(const float* __restrict__ Xp, const float* __restrict__ epsp) {
    const int tid  = threadIdx.x;
    const int warp = tid >> 5;
    const int lane = tid & 31;
    const int ns   = blockIdx.y;
    const int mwb  = blockIdx.x * M_CTA + warp * 32;   // warp m-base
    const int s0   = ns * NSTEPS;                      // first n-step

    const float e = *epsp;
    const ull one2 = splat2(1.0f);

    // eps-scaled Xp for this thread's 4 rows
    ull exs[4], eys[4], ezs[4];
#pragma unroll
    for (int i = 0; i < 4; i++) {
        int tile = i >> 1, u = i & 1;
        int m = mwb + tile * 16 + u * 8 + (lane >> 2);
        exs[i] = splat2(e * Xp[m * 3 + 0]);
        eys[i] = splat2(e * Xp[m * 3 + 1]);
        ezs[i] = splat2(e * Xp[m * 3 + 2]);
    }

    float acc[2][8][4];
#pragma unroll
    for (int t = 0; t < 2; t++)
#pragma unroll
        for (int k = 0; k < 8; k++)
#pragma unroll
            for (int j = 0; j < 4; j++) acc[t][k][j] = 0.0f;

    const float* xp = g_Xpk + ((size_t)s0 * 8 + (lane & 3)) * 8;
    const uint4* bf = reinterpret_cast<const uint4*>(g_Bfrag) + (size_t)s0 * 8 * 32 + lane;

    // prime the pipeline: ktp0/ktp1 fragments of step 0
    uint4 b0 = __ldg(bf + 0 * 32);
    uint4 b1 = __ldg(bf + 1 * 32);
    uint4 b2 = __ldg(bf + 2 * 32);
    uint4 b3 = __ldg(bf + 3 * 32);

    for (int s = 0; s < NSTEPS; s++) {
        // coords for this step
        ulonglong2 xy0 = *reinterpret_cast<const ulonglong2*>(xp);
        ull        zz0 = *reinterpret_cast<const ull*>(xp + 4);
        ulonglong2 xy1 = *reinterpret_cast<const ulonglong2*>(xp + 32);
        ull        zz1 = *reinterpret_cast<const ull*>(xp + 36);
        xp += 64;

        // phi chain (B loads for ktp0/1 already in flight from previous iter)
        uint32_t ah[2][4], al[2][4];
#pragma unroll
        for (int tile = 0; tile < 2; tile++) {
#pragma unroll
            for (int u = 0; u < 2; u++) {
                int ci = tile * 2 + u;
#pragma unroll
                for (int p = 0; p < 2; p++) {
                    ull dx = fadd2(exs[ci], p ? xy1.x : xy0.x);
                    ull dy = fadd2(eys[ci], p ? xy1.y : xy0.y);
                    ull dz = fadd2(ezs[ci], p ? zz1 : zz0);
                    ull tt = ffma2(dx, dx, ffma2(dy, dy, ffma2(dz, dz, one2)));
                    float t0, t1; unpack2(tt, t0, t1);
                    float sq0 = fast_sqrt(t0), sq1 = fast_sqrt(t1);
                    uint32_t hb;
                    asm("cvt.rn.bf16x2.f32 %0, %1, %2;" : "=r"(hb) : "f"(sq1), "f"(sq0));
                    float h0 = __uint_as_float(hb << 16);
                    float h1 = __uint_as_float(hb & 0xffff0000u);
                    float l0 = sq0 - h0, l1 = sq1 - h1;
                    uint32_t lb;
                    asm("cvt.rn.bf16x2.f32 %0, %1, %2;" : "=r"(lb) : "f"(l1), "f"(l0));
                    ah[tile][u + 2 * p] = hb;
                    al[tile][u + 2 * p] = lb;
                }
            }
        }

        // prefetch ktp2/ktp3 of this step
        uint4 n0 = __ldg(bf + 4 * 32);
        uint4 n1 = __ldg(bf + 5 * 32);
        uint4 n2 = __ldg(bf + 6 * 32);
        uint4 n3 = __ldg(bf + 7 * 32);
        bf += 8 * 32;

        // ktp0 (b0 = hi, b1 = lo)
#pragma unroll
        for (int tile = 0; tile < 2; tile++) {
            float* a0 = acc[tile][0];
            mma_bf16(a0, ah[tile][0], ah[tile][1], ah[tile][2], ah[tile][3], b0.x, b0.y);
            mma_bf16(a0, ah[tile][0], ah[tile][1], ah[tile][2], ah[tile][3], b1.x, b1.y);
            mma_bf16(a0, al[tile][0], al[tile][1], al[tile][2], al[tile][3], b0.x, b0.y);
            float* a1 = acc[tile][1];
            mma_bf16(a1, ah[tile][0], ah[tile][1], ah[tile][2], ah[tile][3], b0.z, b0.w);
            mma_bf16(a1, ah[tile][0], ah[tile][1], ah[tile][2], ah[tile][3], b1.z, b1.w);
            mma_bf16(a1, al[tile][0], al[tile][1], al[tile][2], al[tile][3], b0.z, b0.w);
        }
        // ktp1 (b2, b3)
#pragma unroll
        for (int tile = 0; tile < 2; tile++) {
            float* a0 = acc[tile][2];
            mma_bf16(a0, ah[tile][0], ah[tile][1], ah[tile][2], ah[tile][3], b2.x, b2.y);
            mma_bf16(a0, ah[tile][0], ah[tile][1], ah[tile][2], ah[tile][3], b3.x, b3.y);
            mma_bf16(a0, al[tile][0], al[tile][1], al[tile][2], al[tile][3], b2.x, b2.y);
            float* a1 = acc[tile][3];
            mma_bf16(a1, ah[tile][0], ah[tile][1], ah[tile][2], ah[tile][3], b2.z, b2.w);
            mma_bf16(a1, ah[tile][0], ah[tile][1], ah[tile][2], ah[tile][3], b3.z, b3.w);
            mma_bf16(a1, al[tile][0], al[tile][1], al[tile][2], al[tile][3], b2.z, b2.w);
        }

        // prefetch ktp0/ktp1 of NEXT step (pad array guarantees safety at the end)
        b0 = __ldg(bf + 0 * 32);
        b1 = __ldg(bf + 1 * 32);
        b2 = __ldg(bf + 2 * 32);
        b3 = __ldg(bf + 3 * 32);

        // ktp2 (n0, n1)
#pragma unroll
        for (int tile = 0; tile < 2; tile++) {
            float* a0 = acc[tile][4];
            mma_bf16(a0, ah[tile][0], ah[tile][1], ah[tile][2], ah[tile][3], n0.x, n0.y);
            mma_bf16(a0, ah[tile][0], ah[tile][1], ah[tile][2], ah[tile][3], n1.x, n1.y);
            mma_bf16(a0, al[tile][0], al[tile][1], al[tile][2], al[tile][3], n0.x, n0.y);
            float* a1 = acc[tile][5];
            mma_bf16(a1, ah[tile][0], ah[tile][1], ah[tile][2], ah[tile][3], n0.z, n0.w);
            mma_bf16(a1, ah[tile][0], ah[tile][1], ah[tile][2], ah[tile][3], n1.z, n1.w);
            mma_bf16(a1, al[tile][0], al[tile][1], al[tile][2], al[tile][3], n0.z, n0.w);
        }
        // ktp3 (n2, n3)
#pragma unroll
        for (int tile = 0; tile < 2; tile++) {
            float* a0 = acc[tile][6];
            mma_bf16(a0, ah[tile][0], ah[tile][1], ah[tile][2], ah[tile][3], n2.x, n2.y);
            mma_bf16(a0, ah[tile][0], ah[tile][1], ah[tile][2], ah[tile][3], n3.x, n3.y);
            mma_bf16(a0, al[tile][0], al[tile][1], al[tile][2], al[tile][3], n2.x, n2.y);
            float* a1 = acc[tile][7];
            mma_bf16(a1, ah[tile][0], ah[tile][1], ah[tile][2], ah[tile][3], n2.z, n2.w);
            mma_bf16(a1, ah[tile][0], ah[tile][1], ah[tile][2], ah[tile][3], n3.z, n3.w);
            mma_bf16(a1, al[tile][0], al[tile][1], al[tile][2], al[tile][3], n2.z, n2.w);
        }
    }

    // epilogue: write partials
    float* part = g_part[ns];
#pragma unroll
    for (int tile = 0; tile < 2; tile++) {
        int rbase = mwb + tile * 16 + (lane >> 2);
#pragma unroll
        for (int kt = 0; kt < 8; kt++) {
            int c = kt * 8 + (lane & 3) * 2;
            *reinterpret_cast<float2*>(&part[(size_t)rbase * K_DIM + c]) =
                make_float2(acc[tile][kt][0], acc[tile][kt][1]);
            *reinterpret_cast<float2*>(&part[(size_t)(rbase + 8) * K_DIM + c]) =
                make_float2(acc[tile][kt][2], acc[tile][kt][3]);
        }
    }
}

// ---- reduce ----
__global__ __launch_bounds__(256)
void reduce_parts(float* __restrict__ out) {
    int i = blockIdx.x * 256 + threadIdx.x;
    float4 a = reinterpret_cast<const float4*>(g_part[0])[i];
    float4 b = reinterpret_cast<const float4*>(g_part[1])[i];
    float4 c = reinterpret_cast<const float4*>(g_part[2])[i];
    float4 d = reinterpret_cast<const float4*>(g_part[3])[i];
    float4 r;
    r.x = (a.x + b.x) + (c.x + d.x);
    r.y = (a.y + b.y) + (c.y + d.y);
    r.z = (a.z + b.z) + (c.z + d.z);
    r.w = (a.w + b.w) + (c.w + d.w);
    reinterpret_cast<float4*>(out)[i] = r;
}

// ---- dummy: pads launch count so ncu (-s 5) captures rbf_hmma of call 2 ----
__global__ void dummy_noop() {}

extern "C" void kernel_launch(void* const* d_in, const int* in_sizes, int n_in,
                              void* d_out, int out_size) {
    const float* Xp  = (const float*)d_in[0];
    const float* X   = (const float*)d_in[1];
    const float* W   = (const float*)d_in[2];
    const float* eps = (const float*)d_in[3];
    float* out = (float*)d_out;

    prep_all<<<BFRAG_U32 / 256, 256>>>(W, X, eps);

    dim3 grid(M_DIM / M_CTA, NSPLIT);   // 128 x 4 = 512 CTAs
    rbf_hmma<<<grid, THREADS>>>(Xp, eps);

    reduce_parts<<<(M_DIM * K_DIM / 4) / 256, 256>>>(out);

    dummy_noop<<<1, 32>>>();
}

// round 9
// speedup vs baseline: 1.1593x; 1.1593x over previous
#include <cuda_runtime.h>
#include <cuda_bf16.h>
#include <cstdint>

#define M_DIM 16384
#define N_DIM 8192
#define K_DIM 64

#define THREADS 128            // 4 warps
#define M_CTA 128              // warp covers 32 m
#define NSPLIT 4
#define NRANGE (N_DIM / NSPLIT)      // 2048
#define NSTEPS (NRANGE / 16)         // 128 per CTA

#define BFRAG_U32 (512 * 8 * 32 * 4)    // 524288 u32 = 2MB (tf32 fragments)
#define NPAIRS (N_DIM / 2)

typedef unsigned long long ull;

// ---- device scratch ----
// tf32 B fragments: u32 idx = ((s*8 + ktile)*32 + lane)*4 + j
//   j bit0 -> +4 n (b0/b1), j bit1 -> +8 n (k-chunk)
__device__ uint32_t g_Bfrag[BFRAG_U32];
// X pair coords: pair P = s*8 + c*4 + b covers n = s*16 + c*8 + b and n+4,
// stored negated & eps-scaled: {-ex0,-ex1, -ey0,-ey1, -ez0,-ez1, 0,0}
__device__ float g_Xpk[NPAIRS * 8];
__device__ float g_part[NSPLIT][M_DIM * K_DIM];          // partials, 16MB

// ---- helpers ----
__device__ __forceinline__ ull ffma2(ull a, ull b, ull c) {
    ull d; asm("fma.rn.f32x2 %0, %1, %2, %3;" : "=l"(d) : "l"(a), "l"(b), "l"(c)); return d;
}
__device__ __forceinline__ ull fadd2(ull a, ull b) {
    ull d; asm("add.rn.f32x2 %0, %1, %2;" : "=l"(d) : "l"(a), "l"(b)); return d;
}
__device__ __forceinline__ ull splat2(float v) {
    ull d; asm("mov.b64 %0, {%1, %1};" : "=l"(d) : "f"(v)); return d;
}
__device__ __forceinline__ void unpack2(ull p, float& lo, float& hi) {
    asm("mov.b64 {%0, %1}, %2;" : "=f"(lo), "=f"(hi) : "l"(p));
}
__device__ __forceinline__ float fast_sqrt(float x) {
    float r; asm("sqrt.approx.f32 %0, %1;" : "=f"(r) : "f"(x)); return r;
}
__device__ __forceinline__ uint32_t to_tf32(float x) {
    uint32_t r; asm("cvt.rna.tf32.f32 %0, %1;" : "=r"(r) : "f"(x)); return r;
}
__device__ __forceinline__ void mma_tf32(float* d, uint32_t a0, uint32_t a1,
                                         uint32_t a2, uint32_t a3,
                                         uint32_t b0, uint32_t b1) {
    asm volatile(
        "mma.sync.aligned.m16n8k8.row.col.f32.tf32.tf32.f32 "
        "{%0,%1,%2,%3}, {%4,%5,%6,%7}, {%8,%9}, {%0,%1,%2,%3};"
        : "+f"(d[0]), "+f"(d[1]), "+f"(d[2]), "+f"(d[3])
        : "r"(a0), "r"(a1), "r"(a2), "r"(a3), "r"(b0), "r"(b1));
}

// ---- merged prep: X pairs + W tf32 fragment shredding ----
__global__ __launch_bounds__(256)
void prep_all(const float* __restrict__ W, const float* __restrict__ X,
              const float* __restrict__ epsp) {
    int idx = blockIdx.x * 256 + threadIdx.x;

    if (idx < NPAIRS) {
        // pair P: s = P>>3, c = (P>>2)&1, b = P&3 -> n, n+4
        float e = *epsp;
        int s = idx >> 3, c = (idx >> 2) & 1, b = idx & 3;
        int n = s * 16 + c * 8 + b;
        const float* x0 = X + (size_t)n * 3;
        const float* x1 = X + (size_t)(n + 4) * 3;
        float* o = g_Xpk + (size_t)idx * 8;
        o[0] = -e * x0[0]; o[1] = -e * x1[0];
        o[2] = -e * x0[1]; o[3] = -e * x1[1];
        o[4] = -e * x0[2]; o[5] = -e * x1[2];
        o[6] = 0.0f; o[7] = 0.0f;
    }

    // B fragment: idx covers BFRAG_U32
    {
        int j     = idx & 3;
        int lane  = (idx >> 2) & 31;
        int ktile = (idx >> 7) & 7;
        int s     = idx >> 10;
        int n     = s * 16 + ((j >> 1) << 3) + (lane & 3) + ((j & 1) << 2);
        int kout  = ktile * 8 + (lane >> 2);
        float w = W[(size_t)kout * N_DIM + n];
        uint32_t t; asm("cvt.rna.tf32.f32 %0, %1;" : "=r"(t) : "f"(w));
        g_Bfrag[idx] = t;
    }
}

// ---- main kernel ----
__global__ __launch_bounds__(THREADS, 4)
void rbf_tf32(const float* __restrict__ Xp, const float* __restrict__ epsp) {
    const int tid  = threadIdx.x;
    const int warp = tid >> 5;
    const int lane = tid & 31;
    const int ns   = blockIdx.y;
    const int mwb  = blockIdx.x * M_CTA + warp * 32;   // warp m-base
    const int s0   = ns * NSTEPS;                      // first n-step

    const float e = *epsp;
    const ull one2 = splat2(1.0f);

    // eps-scaled Xp for this thread's 4 rows: ci = mtile*2 + u
    ull exs[4], eys[4], ezs[4];
#pragma unroll
    for (int i = 0; i < 4; i++) {
        int mtile = i >> 1, u = i & 1;
        int m = mwb + mtile * 16 + u * 8 + (lane >> 2);
        exs[i] = splat2(e * Xp[m * 3 + 0]);
        eys[i] = splat2(e * Xp[m * 3 + 1]);
        ezs[i] = splat2(e * Xp[m * 3 + 2]);
    }

    float acc[2][8][4];
#pragma unroll
    for (int t = 0; t < 2; t++)
#pragma unroll
        for (int k = 0; k < 8; k++)
#pragma unroll
            for (int j = 0; j < 4; j++) acc[t][k][j] = 0.0f;

    const float* xp = g_Xpk + ((size_t)s0 * 8 + (lane & 3)) * 8;
    const uint4* bf = reinterpret_cast<const uint4*>(g_Bfrag) + (size_t)s0 * 8 * 32 + lane;

    for (int s = 0; s < NSTEPS; s++) {
        // prefetch B fragments for ktiles 0-3 (in flight during phi chain)
        uint4 bfr0 = __ldg(bf + 0 * 32);
        uint4 bfr1 = __ldg(bf + 1 * 32);
        uint4 bfr2 = __ldg(bf + 2 * 32);
        uint4 bfr3 = __ldg(bf + 3 * 32);

        // coords: chunk0 pair at +0, chunk1 pair at +32 floats
        ulonglong2 xy0 = *reinterpret_cast<const ulonglong2*>(xp);
        ull        zz0 = *reinterpret_cast<const ull*>(xp + 4);
        ulonglong2 xy1 = *reinterpret_cast<const ulonglong2*>(xp + 32);
        ull        zz1 = *reinterpret_cast<const ull*>(xp + 36);
        xp += 64;

        // phi -> tf32 A fragments: a[mtile][c][reg], reg = u + 2*v
        uint32_t afr[2][2][4];
#pragma unroll
        for (int mtile = 0; mtile < 2; mtile++) {
#pragma unroll
            for (int u = 0; u < 2; u++) {
                int ci = mtile * 2 + u;
#pragma unroll
                for (int c = 0; c < 2; c++) {
                    ull dx = fadd2(exs[ci], c ? xy1.x : xy0.x);
                    ull dy = fadd2(eys[ci], c ? xy1.y : xy0.y);
                    ull dz = fadd2(ezs[ci], c ? zz1 : zz0);
                    ull tt = ffma2(dx, dx, ffma2(dy, dy, ffma2(dz, dz, one2)));
                    float t0, t1; unpack2(tt, t0, t1);
                    afr[mtile][c][u]     = to_tf32(fast_sqrt(t0));   // v=0 (n)
                    afr[mtile][c][u + 2] = to_tf32(fast_sqrt(t1));   // v=1 (n+4)
                }
            }
        }

        // prefetch B fragments for ktiles 4-7
        uint4 bfr4 = __ldg(bf + 4 * 32);
        uint4 bfr5 = __ldg(bf + 5 * 32);
        uint4 bfr6 = __ldg(bf + 6 * 32);
        uint4 bfr7 = __ldg(bf + 7 * 32);
        bf += 8 * 32;

        // MMAs: 8 ktiles x 2 mtiles x 2 chunks = 32 per step
#pragma unroll
        for (int mtile = 0; mtile < 2; mtile++) {
            const uint32_t* a0 = afr[mtile][0];
            const uint32_t* a1 = afr[mtile][1];
            mma_tf32(acc[mtile][0], a0[0], a0[1], a0[2], a0[3], bfr0.x, bfr0.y);
            mma_tf32(acc[mtile][0], a1[0], a1[1], a1[2], a1[3], bfr0.z, bfr0.w);
            mma_tf32(acc[mtile][1], a0[0], a0[1], a0[2], a0[3], bfr1.x, bfr1.y);
            mma_tf32(acc[mtile][1], a1[0], a1[1], a1[2], a1[3], bfr1.z, bfr1.w);
            mma_tf32(acc[mtile][2], a0[0], a0[1], a0[2], a0[3], bfr2.x, bfr2.y);
            mma_tf32(acc[mtile][2], a1[0], a1[1], a1[2], a1[3], bfr2.z, bfr2.w);
            mma_tf32(acc[mtile][3], a0[0], a0[1], a0[2], a0[3], bfr3.x, bfr3.y);
            mma_tf32(acc[mtile][3], a1[0], a1[1], a1[2], a1[3], bfr3.z, bfr3.w);
            mma_tf32(acc[mtile][4], a0[0], a0[1], a0[2], a0[3], bfr4.x, bfr4.y);
            mma_tf32(acc[mtile][4], a1[0], a1[1], a1[2], a1[3], bfr4.z, bfr4.w);
            mma_tf32(acc[mtile][5], a0[0], a0[1], a0[2], a0[3], bfr5.x, bfr5.y);
            mma_tf32(acc[mtile][5], a1[0], a1[1], a1[2], a1[3], bfr5.z, bfr5.w);
            mma_tf32(acc[mtile][6], a0[0], a0[1], a0[2], a0[3], bfr6.x, bfr6.y);
            mma_tf32(acc[mtile][6], a1[0], a1[1], a1[2], a1[3], bfr6.z, bfr6.w);
            mma_tf32(acc[mtile][7], a0[0], a0[1], a0[2], a0[3], bfr7.x, bfr7.y);
            mma_tf32(acc[mtile][7], a1[0], a1[1], a1[2], a1[3], bfr7.z, bfr7.w);
        }
    }

    // epilogue: write partials (same C-fragment layout as m16n8k16)
    float* part = g_part[ns];
#pragma unroll
    for (int mtile = 0; mtile < 2; mtile++) {
        int rbase = mwb + mtile * 16 + (lane >> 2);
#pragma unroll
        for (int kt = 0; kt < 8; kt++) {
            int c = kt * 8 + (lane & 3) * 2;
            *reinterpret_cast<float2*>(&part[(size_t)rbase * K_DIM + c]) =
                make_float2(acc[mtile][kt][0], acc[mtile][kt][1]);
            *reinterpret_cast<float2*>(&part[(size_t)(rbase + 8) * K_DIM + c]) =
                make_float2(acc[mtile][kt][2], acc[mtile][kt][3]);
        }
    }
}

// ---- reduce ----
__global__ __launch_bounds__(256)
void reduce_parts(float* __restrict__ out) {
    int i = blockIdx.x * 256 + threadIdx.x;
    float4 a = reinterpret_cast<const float4*>(g_part[0])[i];
    float4 b = reinterpret_cast<const float4*>(g_part[1])[i];
    float4 c = reinterpret_cast<const float4*>(g_part[2])[i];
    float4 d = reinterpret_cast<const float4*>(g_part[3])[i];
    float4 r;
    r.x = (a.x + b.x) + (c.x + d.x);
    r.y = (a.y + b.y) + (c.y + d.y);
    r.z = (a.z + b.z) + (c.z + d.z);
    r.w = (a.w + b.w) + (c.w + d.w);
    reinterpret_cast<float4*>(out)[i] = r;
}

extern "C" void kernel_launch(void* const* d_in, const int* in_sizes, int n_in,
                              void* d_out, int out_size) {
    const float* Xp  = (const float*)d_in[0];
    const float* X   = (const float*)d_in[1];
    const float* W   = (const float*)d_in[2];
    const float* eps = (const float*)d_in[3];
    float* out = (float*)d_out;

    prep_all<<<BFRAG_U32 / 256, 256>>>(W, X, eps);

    dim3 grid(M_DIM / M_CTA, NSPLIT);   // 128 x 4 = 512 CTAs
    rbf_tf32<<<grid, THREADS>>>(Xp, eps);

    reduce_parts<<<(M_DIM * K_DIM / 4) / 256, 256>>>(out);
}

// round 10
// speedup vs baseline: 1.8699x; 1.6130x over previous
#include <cuda_runtime.h>
#include <cuda_fp16.h>
#include <cstdint>

#define M_DIM 16384
#define N_DIM 8192
#define K_DIM 64

#define THREADS 128            // 4 warps
#define M_CTA 128              // warp covers 32 m
#define NSPLIT 4
#define NRANGE (N_DIM / NSPLIT)      // 2048
#define NSTEPS (NRANGE / 16)         // 128 per CTA

// fp16 B fragments: u32 idx = ((s*4 + ktp)*32 + lane)*4 + j
//   j: {kt_even k-chunk0, kt_even k-chunk1, kt_odd k-chunk0, kt_odd k-chunk1}
#define BFRAG_U32 (512 * 4 * 32 * 4)    // 262144 u32 = 1MB
#define NPAIRS (N_DIM / 2)

typedef unsigned long long ull;

// ---- device scratch ----
__device__ uint32_t g_Bfrag[BFRAG_U32];
__device__ float g_Xpk[NPAIRS * 8];              // adjacent n-pairs, eps-scaled, negated
__device__ float g_part[NSPLIT][M_DIM * K_DIM];  // partials, 16MB

// ---- helpers ----
__device__ __forceinline__ ull ffma2(ull a, ull b, ull c) {
    ull d; asm("fma.rn.f32x2 %0, %1, %2, %3;" : "=l"(d) : "l"(a), "l"(b), "l"(c)); return d;
}
__device__ __forceinline__ ull fadd2(ull a, ull b) {
    ull d; asm("add.rn.f32x2 %0, %1, %2;" : "=l"(d) : "l"(a), "l"(b)); return d;
}
__device__ __forceinline__ ull splat2(float v) {
    ull d; asm("mov.b64 %0, {%1, %1};" : "=l"(d) : "f"(v)); return d;
}
__device__ __forceinline__ void unpack2(ull p, float& lo, float& hi) {
    asm("mov.b64 {%0, %1}, %2;" : "=f"(lo), "=f"(hi) : "l"(p));
}
__device__ __forceinline__ float fast_sqrt(float x) {
    float r; asm("sqrt.approx.f32 %0, %1;" : "=f"(r) : "f"(x)); return r;
}
__device__ __forceinline__ void mma_fp16(float* d, uint32_t a0, uint32_t a1,
                                         uint32_t a2, uint32_t a3,
                                         uint32_t b0, uint32_t b1) {
    asm volatile(
        "mma.sync.aligned.m16n8k16.row.col.f32.f16.f16.f32 "
        "{%0,%1,%2,%3}, {%4,%5,%6,%7}, {%8,%9}, {%0,%1,%2,%3};"
        : "+f"(d[0]), "+f"(d[1]), "+f"(d[2]), "+f"(d[3])
        : "r"(a0), "r"(a1), "r"(a2), "r"(a3), "r"(b0), "r"(b1));
}

// ---- merged prep: X pairs + W fp16 fragment shredding ----
__global__ __launch_bounds__(256)
void prep_all(const float* __restrict__ W, const float* __restrict__ X,
              const float* __restrict__ epsp) {
    int idx = blockIdx.x * 256 + threadIdx.x;

    if (idx < NPAIRS) {   // adjacent pair p -> n = 2p, 2p+1
        float e = *epsp;
        const float* x0 = X + (size_t)(2 * idx) * 3;
        float* o = g_Xpk + (size_t)idx * 8;
        o[0] = -e * x0[0]; o[1] = -e * x0[3];
        o[2] = -e * x0[1]; o[3] = -e * x0[4];
        o[4] = -e * x0[2]; o[5] = -e * x0[5];
        o[6] = 0.0f; o[7] = 0.0f;
    }

    // B fragment shred (idx covers BFRAG_U32) — R5 mapping, h-dim removed
    {
        int j   = idx & 3;
        int t   = (idx >> 2) & 31;
        int ktp = (idx >> 7) & 3;
        int s   = idx >> 9;

        int kt = ktp * 2 + (j >> 1);
        int km = (t & 3) * 2 + (j & 1) * 8;   // contraction n within step
        int nm = t >> 2;                      // output k within tile
        int kout = kt * 8 + nm;
        int n = s * 16 + km;

        float w0 = W[(size_t)kout * N_DIM + n];
        float w1 = W[(size_t)kout * N_DIM + n + 1];
        uint32_t packed;
        asm("cvt.rn.f16x2.f32 %0, %1, %2;" : "=r"(packed) : "f"(w1), "f"(w0));
        g_Bfrag[idx] = packed;
    }
}

// ---- main kernel ----
__global__ __launch_bounds__(THREADS, 4)
void rbf_fp16(const float* __restrict__ Xp, const float* __restrict__ epsp) {
    const int tid  = threadIdx.x;
    const int warp = tid >> 5;
    const int lane = tid & 31;
    const int ns   = blockIdx.y;
    const int mwb  = blockIdx.x * M_CTA + warp * 32;   // warp m-base
    const int s0   = ns * NSTEPS;                      // first n-step

    const float e = *epsp;
    const ull one2 = splat2(1.0f);

    // eps-scaled Xp for this thread's 4 rows: ci = mtile*2 + u
    ull exs[4], eys[4], ezs[4];
#pragma unroll
    for (int i = 0; i < 4; i++) {
        int mtile = i >> 1, u = i & 1;
        int m = mwb + mtile * 16 + u * 8 + (lane >> 2);
        exs[i] = splat2(e * Xp[m * 3 + 0]);
        eys[i] = splat2(e * Xp[m * 3 + 1]);
        ezs[i] = splat2(e * Xp[m * 3 + 2]);
    }

    float acc[2][8][4];
#pragma unroll
    for (int t = 0; t < 2; t++)
#pragma unroll
        for (int k = 0; k < 8; k++)
#pragma unroll
            for (int j = 0; j < 4; j++) acc[t][k][j] = 0.0f;

    // thread's pairs: q0 = s*8 + (lane&3)  (n = 16s + 2(lane&3)), q1 = q0+4 (n+8)
    const float* xp = g_Xpk + ((size_t)s0 * 8 + (lane & 3)) * 8;
    const uint4* bf = reinterpret_cast<const uint4*>(g_Bfrag) + (size_t)s0 * 4 * 32 + lane;

    for (int s = 0; s < NSTEPS; s++) {
        // prefetch all B fragments for this step (4 x LDG.128)
        uint4 bfr0 = __ldg(bf + 0 * 32);
        uint4 bfr1 = __ldg(bf + 1 * 32);
        uint4 bfr2 = __ldg(bf + 2 * 32);
        uint4 bfr3 = __ldg(bf + 3 * 32);
        bf += 4 * 32;

        // coords for the two k-chunk pairs
        ulonglong2 xy0 = *reinterpret_cast<const ulonglong2*>(xp);
        ull        zz0 = *reinterpret_cast<const ull*>(xp + 4);
        ulonglong2 xy1 = *reinterpret_cast<const ulonglong2*>(xp + 32);
        ull        zz1 = *reinterpret_cast<const ull*>(xp + 36);
        xp += 64;

        // phi chain -> fp16 A fragments: ah[mtile][u + 2*p]
        uint32_t ah[2][4];
#pragma unroll
        for (int mtile = 0; mtile < 2; mtile++) {
#pragma unroll
            for (int u = 0; u < 2; u++) {
                int ci = mtile * 2 + u;
#pragma unroll
                for (int p = 0; p < 2; p++) {
                    ull dx = fadd2(exs[ci], p ? xy1.x : xy0.x);
                    ull dy = fadd2(eys[ci], p ? xy1.y : xy0.y);
                    ull dz = fadd2(ezs[ci], p ? zz1 : zz0);
                    ull tt = ffma2(dx, dx, ffma2(dy, dy, ffma2(dz, dz, one2)));
                    float t0, t1; unpack2(tt, t0, t1);
                    float sq0 = fast_sqrt(t0), sq1 = fast_sqrt(t1);
                    uint32_t hb;
                    asm("cvt.rn.f16x2.f32 %0, %1, %2;" : "=r"(hb) : "f"(sq1), "f"(sq0));
                    ah[mtile][u + 2 * p] = hb;
                }
            }
        }

        // MMAs: 4 ktp x 2 kt x 2 mtiles = 16 per step
#pragma unroll
        for (int mtile = 0; mtile < 2; mtile++) {
            uint32_t* a = ah[mtile];
            mma_fp16(acc[mtile][0], a[0], a[1], a[2], a[3], bfr0.x, bfr0.y);
            mma_fp16(acc[mtile][1], a[0], a[1], a[2], a[3], bfr0.z, bfr0.w);
            mma_fp16(acc[mtile][2], a[0], a[1], a[2], a[3], bfr1.x, bfr1.y);
            mma_fp16(acc[mtile][3], a[0], a[1], a[2], a[3], bfr1.z, bfr1.w);
            mma_fp16(acc[mtile][4], a[0], a[1], a[2], a[3], bfr2.x, bfr2.y);
            mma_fp16(acc[mtile][5], a[0], a[1], a[2], a[3], bfr2.z, bfr2.w);
            mma_fp16(acc[mtile][6], a[0], a[1], a[2], a[3], bfr3.x, bfr3.y);
            mma_fp16(acc[mtile][7], a[0], a[1], a[2], a[3], bfr3.z, bfr3.w);
        }
    }

    // epilogue: write partials
    float* part = g_part[ns];
#pragma unroll
    for (int mtile = 0; mtile < 2; mtile++) {
        int rbase = mwb + mtile * 16 + (lane >> 2);
#pragma unroll
        for (int kt = 0; kt < 8; kt++) {
            int c = kt * 8 + (lane & 3) * 2;
            *reinterpret_cast<float2*>(&part[(size_t)rbase * K_DIM + c]) =
                make_float2(acc[mtile][kt][0], acc[mtile][kt][1]);
            *reinterpret_cast<float2*>(&part[(size_t)(rbase + 8) * K_DIM + c]) =
                make_float2(acc[mtile][kt][2], acc[mtile][kt][3]);
        }
    }
}

// ---- reduce ----
__global__ __launch_bounds__(256)
void reduce_parts(float* __restrict__ out) {
    int i = blockIdx.x * 256 + threadIdx.x;
    float4 a = reinterpret_cast<const float4*>(g_part[0])[i];
    float4 b = reinterpret_cast<const float4*>(g_part[1])[i];
    float4 c = reinterpret_cast<const float4*>(g_part[2])[i];
    float4 d = reinterpret_cast<const float4*>(g_part[3])[i];
    float4 r;
    r.x = (a.x + b.x) + (c.x + d.x);
    r.y = (a.y + b.y) + (c.y + d.y);
    r.z = (a.z + b.z) + (c.z + d.z);
    r.w = (a.w + b.w) + (c.w + d.w);
    reinterpret_cast<float4*>(out)[i] = r;
}

extern "C" void kernel_launch(void* const* d_in, const int* in_sizes, int n_in,
                              void* d_out, int out_size) {
    const float* Xp  = (const float*)d_in[0];
    const float* X   = (const float*)d_in[1];
    const float* W   = (const float*)d_in[2];
    const float* eps = (const float*)d_in[3];
    float* out = (float*)d_out;

    prep_all<<<BFRAG_U32 / 256, 256>>>(W, X, eps);

    dim3 grid(M_DIM / M_CTA, NSPLIT);   // 128 x 4 = 512 CTAs
    rbf_fp16<<<grid, THREADS>>>(Xp, eps);

    reduce_parts<<<(M_DIM * K_DIM / 4) / 256, 256>>>(out);
}

// round 11
// speedup vs baseline: 2.1406x; 1.1448x over previous
#include <cuda_runtime.h>
#include <cuda_fp16.h>
#include <cstdint>

#define M_DIM 16384
#define N_DIM 8192
#define K_DIM 64

#define THREADS 128            // 4 warps
#define M_CTA 128              // warp covers 32 m
#define NSPLIT 4
#define NRANGE (N_DIM / NSPLIT)      // 2048
#define NSTEPS (NRANGE / 16)         // 128 per CTA

// fp16 B fragments: u32 idx = ((s*4 + ktp)*32 + lane)*4 + j
#define BFRAG_U32 (512 * 4 * 32 * 4)    // 1MB
#define NPAIRS (N_DIM / 2)

typedef unsigned long long ull;

// ---- device scratch ----
__device__ uint32_t g_Bfrag[BFRAG_U32];
// per n-pair: {bx0,bx1, by0,by1, bz0,bz1, c0,c1}; b=-2e^2 x, c=e^2|x|^2+1
__device__ float g_Xpk[NPAIRS * 8];
__device__ float g_part[NSPLIT][M_DIM * K_DIM];  // partials, 16MB

// ---- helpers ----
__device__ __forceinline__ ull ffma2(ull a, ull b, ull c) {
    ull d; asm("fma.rn.f32x2 %0, %1, %2, %3;" : "=l"(d) : "l"(a), "l"(b), "l"(c)); return d;
}
__device__ __forceinline__ ull fadd2(ull a, ull b) {
    ull d; asm("add.rn.f32x2 %0, %1, %2;" : "=l"(d) : "l"(a), "l"(b)); return d;
}
__device__ __forceinline__ ull splat2(float v) {
    ull d; asm("mov.b64 %0, {%1, %1};" : "=l"(d) : "f"(v)); return d;
}
__device__ __forceinline__ void unpack2(ull p, float& lo, float& hi) {
    asm("mov.b64 {%0, %1}, %2;" : "=f"(lo), "=f"(hi) : "l"(p));
}
__device__ __forceinline__ float fast_sqrt(float x) {
    float r; asm("sqrt.approx.f32 %0, %1;" : "=f"(r) : "f"(x)); return r;
}
__device__ __forceinline__ void mma_fp16(float* d, uint32_t a0, uint32_t a1,
                                         uint32_t a2, uint32_t a3,
                                         uint32_t b0, uint32_t b1) {
    asm volatile(
        "mma.sync.aligned.m16n8k16.row.col.f32.f16.f16.f32 "
        "{%0,%1,%2,%3}, {%4,%5,%6,%7}, {%8,%9}, {%0,%1,%2,%3};"
        : "+f"(d[0]), "+f"(d[1]), "+f"(d[2]), "+f"(d[3])
        : "r"(a0), "r"(a1), "r"(a2), "r"(a3), "r"(b0), "r"(b1));
}

// ---- merged prep: X pair vectors + W fp16 fragment shredding ----
__global__ __launch_bounds__(256)
void prep_all(const float* __restrict__ W, const float* __restrict__ X,
              const float* __restrict__ epsp) {
    int idx = blockIdx.x * 256 + threadIdx.x;

    if (idx < NPAIRS) {   // adjacent pair p -> n = 2p, 2p+1
        float e = *epsp;
        float e2 = e * e;
        const float* x0 = X + (size_t)(2 * idx) * 3;
        float a0 = x0[0], a1 = x0[1], a2 = x0[2];
        float b0 = x0[3], b1 = x0[4], b2 = x0[5];
        float* o = g_Xpk + (size_t)idx * 8;
        o[0] = -2.0f * e2 * a0; o[1] = -2.0f * e2 * b0;
        o[2] = -2.0f * e2 * a1; o[3] = -2.0f * e2 * b1;
        o[4] = -2.0f * e2 * a2; o[5] = -2.0f * e2 * b2;
        o[6] = fmaf(e2, a0 * a0 + a1 * a1 + a2 * a2, 1.0f);
        o[7] = fmaf(e2, b0 * b0 + b1 * b1 + b2 * b2, 1.0f);
    }

    // B fragment shred (idx covers BFRAG_U32)
    {
        int j   = idx & 3;
        int t   = (idx >> 2) & 31;
        int ktp = (idx >> 7) & 3;
        int s   = idx >> 9;

        int kt = ktp * 2 + (j >> 1);
        int km = (t & 3) * 2 + (j & 1) * 8;   // contraction n within step
        int nm = t >> 2;                      // output k within tile
        int kout = kt * 8 + nm;
        int n = s * 16 + km;

        float w0 = W[(size_t)kout * N_DIM + n];
        float w1 = W[(size_t)kout * N_DIM + n + 1];
        uint32_t packed;
        asm("cvt.rn.f16x2.f32 %0, %1, %2;" : "=r"(packed) : "f"(w1), "f"(w0));
        g_Bfrag[idx] = packed;
    }
}

// ---- main kernel ----
__global__ __launch_bounds__(THREADS, 4)
void rbf_fp16(const float* __restrict__ Xp, const float* __restrict__ epsp) {
    const int tid  = threadIdx.x;
    const int warp = tid >> 5;
    const int lane = tid & 31;
    const int ns   = blockIdx.y;
    const int mwb  = blockIdx.x * M_CTA + warp * 32;   // warp m-base
    const int s0   = ns * NSTEPS;                      // first n-step

    const float e = *epsp;
    const float e2 = e * e;

    // raw Xp coords + Pm = e^2 |xp|^2 for this thread's 4 rows: ci = mtile*2 + u
    ull xs[4], ys[4], zs[4], pm[4];
#pragma unroll
    for (int i = 0; i < 4; i++) {
        int mtile = i >> 1, u = i & 1;
        int m = mwb + mtile * 16 + u * 8 + (lane >> 2);
        float px = Xp[m * 3 + 0], py = Xp[m * 3 + 1], pz = Xp[m * 3 + 2];
        xs[i] = splat2(px);
        ys[i] = splat2(py);
        zs[i] = splat2(pz);
        pm[i] = splat2(e2 * (px * px + py * py + pz * pz));
    }

    float acc[2][8][4];
#pragma unroll
    for (int t = 0; t < 2; t++)
#pragma unroll
        for (int k = 0; k < 8; k++)
#pragma unroll
            for (int j = 0; j < 4; j++) acc[t][k][j] = 0.0f;

    const float* xp = g_Xpk + ((size_t)s0 * 8 + (lane & 3)) * 8;
    const uint4* bf = reinterpret_cast<const uint4*>(g_Bfrag) + (size_t)s0 * 4 * 32 + lane;

    for (int s = 0; s < NSTEPS; s++) {
        // B fragments for this step (4 x LDG.128)
        uint4 bfr0 = __ldg(bf + 0 * 32);
        uint4 bfr1 = __ldg(bf + 1 * 32);
        uint4 bfr2 = __ldg(bf + 2 * 32);
        uint4 bfr3 = __ldg(bf + 3 * 32);
        bf += 4 * 32;

        // pair vectors: p=0 at +0, p=1 at +32 floats; (bx,by) then (bz,c)
        ulonglong2 A0 = *reinterpret_cast<const ulonglong2*>(xp);
        ulonglong2 B0 = *reinterpret_cast<const ulonglong2*>(xp + 4);
        ulonglong2 A1 = *reinterpret_cast<const ulonglong2*>(xp + 32);
        ulonglong2 B1 = *reinterpret_cast<const ulonglong2*>(xp + 36);
        xp += 64;

        // ---- mtile 0: phi -> fragments, then MMAs; then mtile 1 ----
        uint32_t ah0[4], ah1[4];
#pragma unroll
        for (int u = 0; u < 2; u++) {
            int ci = u;  // mtile 0
#pragma unroll
            for (int p = 0; p < 2; p++) {
                ull base = fadd2(p ? B1.y : B0.y, pm[ci]);
                ull tt = ffma2(xs[ci], p ? A1.x : A0.x,
                         ffma2(ys[ci], p ? A1.y : A0.y,
                         ffma2(zs[ci], p ? B1.x : B0.x, base)));
                float t0, t1; unpack2(tt, t0, t1);
                float sq0 = fast_sqrt(t0), sq1 = fast_sqrt(t1);
                uint32_t hb;
                asm("cvt.rn.f16x2.f32 %0, %1, %2;" : "=r"(hb) : "f"(sq1), "f"(sq0));
                ah0[u + 2 * p] = hb;
            }
        }
        mma_fp16(acc[0][0], ah0[0], ah0[1], ah0[2], ah0[3], bfr0.x, bfr0.y);
        mma_fp16(acc[0][1], ah0[0], ah0[1], ah0[2], ah0[3], bfr0.z, bfr0.w);
        mma_fp16(acc[0][2], ah0[0], ah0[1], ah0[2], ah0[3], bfr1.x, bfr1.y);
        mma_fp16(acc[0][3], ah0[0], ah0[1], ah0[2], ah0[3], bfr1.z, bfr1.w);
        mma_fp16(acc[0][4], ah0[0], ah0[1], ah0[2], ah0[3], bfr2.x, bfr2.y);
        mma_fp16(acc[0][5], ah0[0], ah0[1], ah0[2], ah0[3], bfr2.z, bfr2.w);
        mma_fp16(acc[0][6], ah0[0], ah0[1], ah0[2], ah0[3], bfr3.x, bfr3.y);
        mma_fp16(acc[0][7], ah0[0], ah0[1], ah0[2], ah0[3], bfr3.z, bfr3.w);

#pragma unroll
        for (int u = 0; u < 2; u++) {
            int ci = 2 + u;  // mtile 1
#pragma unroll
            for (int p = 0; p < 2; p++) {
                ull base = fadd2(p ? B1.y : B0.y, pm[ci]);
                ull tt = ffma2(xs[ci], p ? A1.x : A0.x,
                         ffma2(ys[ci], p ? A1.y : A0.y,
                         ffma2(zs[ci], p ? B1.x : B0.x, base)));
                float t0, t1; unpack2(tt, t0, t1);
                float sq0 = fast_sqrt(t0), sq1 = fast_sqrt(t1);
                uint32_t hb;
                asm("cvt.rn.f16x2.f32 %0, %1, %2;" : "=r"(hb) : "f"(sq1), "f"(sq0));
                ah1[u + 2 * p] = hb;
            }
        }
        mma_fp16(acc[1][0], ah1[0], ah1[1], ah1[2], ah1[3], bfr0.x, bfr0.y);
        mma_fp16(acc[1][1], ah1[0], ah1[1], ah1[2], ah1[3], bfr0.z, bfr0.w);
        mma_fp16(acc[1][2], ah1[0], ah1[1], ah1[2], ah1[3], bfr1.x, bfr1.y);
        mma_fp16(acc[1][3], ah1[0], ah1[1], ah1[2], ah1[3], bfr1.z, bfr1.w);
        mma_fp16(acc[1][4], ah1[0], ah1[1], ah1[2], ah1[3], bfr2.x, bfr2.y);
        mma_fp16(acc[1][5], ah1[0], ah1[1], ah1[2], ah1[3], bfr2.z, bfr2.w);
        mma_fp16(acc[1][6], ah1[0], ah1[1], ah1[2], ah1[3], bfr3.x, bfr3.y);
        mma_fp16(acc[1][7], ah1[0], ah1[1], ah1[2], ah1[3], bfr3.z, bfr3.w);
    }

    // epilogue: write partials
    float* part = g_part[ns];
#pragma unroll
    for (int mtile = 0; mtile < 2; mtile++) {
        int rbase = mwb + mtile * 16 + (lane >> 2);
#pragma unroll
        for (int kt = 0; kt < 8; kt++) {
            int c = kt * 8 + (lane & 3) * 2;
            *reinterpret_cast<float2*>(&part[(size_t)rbase * K_DIM + c]) =
                make_float2(acc[mtile][kt][0], acc[mtile][kt][1]);
            *reinterpret_cast<float2*>(&part[(size_t)(rbase + 8) * K_DIM + c]) =
                make_float2(acc[mtile][kt][2], acc[mtile][kt][3]);
        }
    }
}

// ---- reduce ----
__global__ __launch_bounds__(256)
void reduce_parts(float* __restrict__ out) {
    int i = blockIdx.x * 256 + threadIdx.x;
    float4 a = reinterpret_cast<const float4*>(g_part[0])[i];
    float4 b = reinterpret_cast<const float4*>(g_part[1])[i];
    float4 c = reinterpret_cast<const float4*>(g_part[2])[i];
    float4 d = reinterpret_cast<const float4*>(g_part[3])[i];
    float4 r;
    r.x = (a.x + b.x) + (c.x + d.x);
    r.y = (a.y + b.y) + (c.y + d.y);
    r.z = (a.z + b.z) + (c.z + d.z);
    r.w = (a.w + b.w) + (c.w + d.w);
    reinterpret_cast<float4*>(out)[i] = r;
}

extern "C" void kernel_launch(void* const* d_in, const int* in_sizes, int n_in,
                              void* d_out, int out_size) {
    const float* Xp  = (const float*)d_in[0];
    const float* X   = (const float*)d_in[1];
    const float* W   = (const float*)d_in[2];
    const float* eps = (const float*)d_in[3];
    float* out = (float*)d_out;

    prep_all<<<BFRAG_U32 / 256, 256>>>(W, X, eps);

    dim3 grid(M_DIM / M_CTA, NSPLIT);   // 128 x 4 = 512 CTAs
    rbf_fp16<<<grid, THREADS>>>(Xp, eps);

    reduce_parts<<<(M_DIM * K_DIM / 4) / 256, 256>>>(out);
}